// round 14
// baseline (speedup 1.0000x reference)
#include <cuda_runtime.h>
#include <cstdint>

// Embedding gather: out[token, :] = weight[input[token], :]
// input: [32768] int32, weight: [50257, 512] f32 (2048B rows), out: [32768, 512] f32
//
// Dual-engine experiment: LDG-gather and TMA-bulk paths each plateau at
// ~3.2-3.5 TB/s cold through DIFFERENT front-end queues (L1tex miss
// tracker vs TMA/bulk issue). This kernel splits CTAs by parity:
//   even CTAs -> warp-per-token LDG float4 copy (measured-best R5 path)
//   odd  CTAs -> cp.async.bulk gmem->smem->gmem staging (R4 path)
// Both populations are co-resident, so both memory engines issue
// concurrently. If their in-flight tracking adds, aggregate bandwidth
// rises; if the LTS/DRAM cap is shared, this is neutral.

#define TOK_PER_CTA 8
#define ROW_BYTES   2048

__global__ __launch_bounds__(256) void embed_gather_dual(
    const int* __restrict__ idx,
    const char* __restrict__ weight,
    char* __restrict__ out,
    int n_tokens)
{
    __shared__ alignas(1024) char buf[TOK_PER_CTA * ROW_BYTES];  // 16KB (TMA CTAs)
    __shared__ int s_rows[TOK_PER_CTA];
    __shared__ alignas(8) unsigned long long mbar;

    const int tid  = threadIdx.x;
    const int base = blockIdx.x * TOK_PER_CTA;
    if (base >= n_tokens) return;
    const int nloc = min(TOK_PER_CTA, n_tokens - base);

    if ((blockIdx.x & 1) == 0) {
        // ---------- LDG path (proven best structure) ----------
        const int warp = tid >> 5;
        const int lane = tid & 31;

        if (tid < TOK_PER_CTA) {
            int t = base + tid;
            s_rows[tid] = (t < n_tokens) ? __ldg(idx + t) : 0;
        }
        __syncthreads();

        if (warp >= nloc) return;
        const int row = s_rows[warp];

        const float4* __restrict__ src =
            (const float4*)(weight + (long long)row * ROW_BYTES) + lane;
        float4* __restrict__ dst =
            (float4*)(out + (long long)(base + warp) * ROW_BYTES) + lane;

        float4 v0 = __ldg(src);
        float4 v1 = __ldg(src + 32);
        float4 v2 = __ldg(src + 64);
        float4 v3 = __ldg(src + 96);

        __stcs(dst,      v0);
        __stcs(dst + 32, v1);
        __stcs(dst + 64, v2);
        __stcs(dst + 96, v3);
    } else {
        // ---------- TMA bulk path ----------
        if (tid != 0) return;   // single-thread issue; no intra-block sync needed

        const uint32_t mbar_a = (uint32_t)__cvta_generic_to_shared(&mbar);
        const uint32_t buf_a  = (uint32_t)__cvta_generic_to_shared(buf);

        asm volatile("mbarrier.init.shared.b64 [%0], 1;" :: "r"(mbar_a) : "memory");
        asm volatile("fence.proxy.async.shared::cta;" ::: "memory");

        // Load the 8 indices (independent LDGs).
        int rows[TOK_PER_CTA];
        #pragma unroll
        for (int i = 0; i < TOK_PER_CTA; i++)
            rows[i] = (i < nloc) ? __ldg(idx + base + i) : 0;

        asm volatile("mbarrier.arrive.expect_tx.shared.b64 _, [%0], %1;"
                     :: "r"(mbar_a), "r"(nloc * ROW_BYTES) : "memory");

        #pragma unroll
        for (int i = 0; i < TOK_PER_CTA; i++) {
            if (i >= nloc) break;
            const char* src = weight + (long long)rows[i] * ROW_BYTES;
            asm volatile(
                "cp.async.bulk.shared::cta.global.mbarrier::complete_tx::bytes "
                "[%0], [%1], %2, [%3];"
                :: "r"(buf_a + i * ROW_BYTES), "l"(src), "r"(ROW_BYTES), "r"(mbar_a)
                : "memory");
        }

        // Wait phase 0.
        asm volatile(
            "{\n\t"
            ".reg .pred p;\n\t"
            "WAIT_%=:\n\t"
            "mbarrier.try_wait.parity.shared.b64 p, [%0], 0, 0x989680;\n\t"
            "@!p bra.uni WAIT_%=;\n\t"
            "}"
            :: "r"(mbar_a) : "memory");

        #pragma unroll
        for (int i = 0; i < TOK_PER_CTA; i++) {
            if (i >= nloc) break;
            char* dst = out + (long long)(base + i) * ROW_BYTES;
            asm volatile(
                "cp.async.bulk.global.shared::cta.bulk_group [%0], [%1], %2;"
                :: "l"(dst), "r"(buf_a + i * ROW_BYTES), "r"(ROW_BYTES)
                : "memory");
        }
        asm volatile("cp.async.bulk.commit_group;" ::: "memory");
        asm volatile("cp.async.bulk.wait_group 0;" ::: "memory");
    }
}

extern "C" void kernel_launch(void* const* d_in, const int* in_sizes, int n_in,
                              void* d_out, int out_size) {
    const int*  idx    = (const int*)d_in[0];     // [8*4096] int32
    const char* weight = (const char*)d_in[1];    // [50257*512] f32 rows
    char*       out    = (char*)d_out;

    int n_tokens = in_sizes[0];                   // 32768
    int blocks   = (n_tokens + TOK_PER_CTA - 1) / TOK_PER_CTA;  // 4096
    embed_gather_dual<<<blocks, 256>>>(idx, weight, out, n_tokens);
}

// round 15
// speedup vs baseline: 1.1214x; 1.1214x over previous
#include <cuda_runtime.h>
#include <cstdint>

// Embedding gather: out[token, :] = weight[input[token], :]
// input: [32768] int32, weight: [50257, 512] f32, out: [32768, 512] f32
//
// FINAL kernel (measured-best, reproduced at 16.83us).
//
// Fourteen experiments established the roofline: steady-state traffic is
// ~115MB/replay (48MB unique weight rows + 67MB output writeback) at
// ~6.85TB/s = ~85% of HBM spec. LDG and TMA front-ends share one LTS/DRAM
// cap (dual-engine split regressed); MLP>4, 256-bit ops, persistent grids,
// cache-residency hints, and CTA-shape changes are all neutral. The two
// structural wins, kept here:
//   1. One warp per token row: 4 independent front-batched float4 loads
//      per thread (MLP=4) — covers DRAM latency without overrunning the
//      L1tex queue.
//   2. Block's 8 indices staged via ONE coalesced load into smem — removes
//      the serial idx-LDG (~600cyc) -> weight-LDG (~600cyc) chain; warps
//      read row ids via 29-cycle LDS.
// Store policy: __stcs evict-first streaming (best measured; write-through
// and evict_last both regress — L2 write buffering matters).

#define WARPS_PER_CTA 8

__global__ __launch_bounds__(WARPS_PER_CTA * 32) void embed_gather_smem_idx(
    const int* __restrict__ idx,
    const float4* __restrict__ weight4,
    float4* __restrict__ out4,
    int n_tokens)
{
    __shared__ int s_rows[WARPS_PER_CTA];

    const int tid  = threadIdx.x;
    const int warp = tid >> 5;
    const int lane = tid & 31;
    const int base = blockIdx.x * WARPS_PER_CTA;

    // One coalesced load fetches all indices for this block.
    if (tid < WARPS_PER_CTA) {
        int t = base + tid;
        s_rows[tid] = (t < n_tokens) ? __ldg(idx + t) : 0;
    }
    __syncthreads();

    const int token = base + warp;
    if (token >= n_tokens) return;
    const int row = s_rows[warp];

    const float4* __restrict__ src = weight4 + (long long)row * 128 + lane;
    float4* __restrict__ dst       = out4    + (long long)token * 128 + lane;

    // 4 independent loads front-batched (MLP=4)
    float4 v0 = __ldg(src);
    float4 v1 = __ldg(src + 32);
    float4 v2 = __ldg(src + 64);
    float4 v3 = __ldg(src + 96);

    __stcs(dst,      v0);
    __stcs(dst + 32, v1);
    __stcs(dst + 64, v2);
    __stcs(dst + 96, v3);
}

extern "C" void kernel_launch(void* const* d_in, const int* in_sizes, int n_in,
                              void* d_out, int out_size) {
    const int*   idx    = (const int*)d_in[0];     // [8*4096] int32
    const float* weight = (const float*)d_in[1];   // [50257*512] f32
    float*       out    = (float*)d_out;

    int n_tokens = in_sizes[0];                    // 32768
    int blocks   = (n_tokens + WARPS_PER_CTA - 1) / WARPS_PER_CTA;  // 4096
    embed_gather_smem_idx<<<blocks, WARPS_PER_CTA * 32>>>(
        idx, (const float4*)weight, (float4*)out, n_tokens);
}